// round 5
// baseline (speedup 1.0000x reference)
#include <cuda_runtime.h>
#include <math.h>

#define NL 512
#define CL 32

// Scratch: planes transposed to [H][W][C] (channel-contiguous, 128B per texel),
// lines transposed to [N][C].
__device__ float g_planes[3][(size_t)NL * NL * CL];   // 96 MB
__device__ float g_lines[3][NL * CL];

// ---------------------------------------------------------------------------
// Transpose planes [C,H,W] -> [H,W,C] via shared tile (coalesced both sides).
// Also handles lines on blockIdx.y == NL (tail work, 3 blocks).
// ---------------------------------------------------------------------------
__global__ void k_transpose(const float* __restrict__ pxy,
                            const float* __restrict__ pyz,
                            const float* __restrict__ pxz,
                            const float* __restrict__ lx,
                            const float* __restrict__ ly,
                            const float* __restrict__ lz)
{
    __shared__ float tile[32][33];
    int plane = blockIdx.z;

    if (blockIdx.y == NL) {
        // lines: [C, NL, 1] -> [NL][C]; 16 n-rows per block (x dim covers NL/16... )
        const float* src = (plane == 0) ? lx : (plane == 1) ? ly : lz;
        // block x in [0, 16): each handles 32 n values
        int n = blockIdx.x * 32 + threadIdx.y;
        int c = threadIdx.x;
        // read coalesced via tile: src[c * NL + n]
        tile[threadIdx.y][threadIdx.x] = src[threadIdx.x * NL + blockIdx.x * 32 + threadIdx.y];
        __syncthreads();
        g_lines[plane][n * CL + c] = tile[threadIdx.y][c] * 0.0f + tile[threadIdx.y][c]; // keep simple
        return;
    }

    const float* src = (plane == 0) ? pxy : (plane == 1) ? pyz : pxz;
    int h  = blockIdx.y;
    int w0 = blockIdx.x * 32;

    // read: lanes sweep w (coalesced), y sweeps channel
    int wx = threadIdx.x, c_in = threadIdx.y;
    tile[c_in][wx] = src[(size_t)c_in * (NL * NL) + (size_t)h * NL + (w0 + wx)];
    __syncthreads();

    // write: lanes sweep channel (contiguous 128B), y sweeps w
    int c = threadIdx.x, wy = threadIdx.y;
    g_planes[plane][((size_t)h * NL + (w0 + wy)) * CL + c] = tile[c][wy];
}

// ---------------------------------------------------------------------------
// Main fused kernel: gather + trilinear-combine + MLP
// ---------------------------------------------------------------------------
__device__ __forceinline__ void grid_coord(float g, int& i0, float& f)
{
    float ix = (g + 1.0f) * 0.5f * (float)(NL - 1);
    float fl = floorf(ix);
    int   i  = (int)fl;
    float fr = ix - fl;
    if (i < 0)      { i = 0;      fr = 0.0f; }
    if (i > NL - 2) { i = NL - 2; fr = 1.0f; }
    i0 = i; f = fr;
}

__device__ __forceinline__ float4 lerp4(float4 a, float4 b, float t)
{
    float4 r;
    r.x = fmaf(t, b.x - a.x, a.x);
    r.y = fmaf(t, b.y - a.y, a.y);
    r.z = fmaf(t, b.z - a.z, a.z);
    r.w = fmaf(t, b.w - a.w, a.w);
    return r;
}

__device__ __forceinline__ float4 bil4(const float* __restrict__ base, int o,
                                       float w00, float w01, float w10, float w11)
{
    const int dW = CL;        // +1 in w
    const int dH = NL * CL;   // +1 in h
    float4 v00 = *(const float4*)(base + o);
    float4 v01 = *(const float4*)(base + o + dW);
    float4 v10 = *(const float4*)(base + o + dH);
    float4 v11 = *(const float4*)(base + o + dH + dW);
    float4 r;
    r.x = v00.x * w00 + v01.x * w01 + v10.x * w10 + v11.x * w11;
    r.y = v00.y * w00 + v01.y * w01 + v10.y * w10 + v11.y * w11;
    r.z = v00.z * w00 + v01.z * w01 + v10.z * w10 + v11.z * w11;
    r.w = v00.w * w00 + v01.w * w01 + v10.w * w10 + v11.w * w11;
    return r;
}

__global__ __launch_bounds__(256)
void k_tensorf(const float* __restrict__ coords,
               const float* __restrict__ W1,
               const float* __restrict__ b1,
               const float* __restrict__ W2,
               const float* __restrict__ b2,
               float* __restrict__ out, int P)
{
    __shared__ float sW1t[128 * CL];  // [j][c]  (transposed for c-vectorized reads)
    __shared__ float sb1[128];
    __shared__ float sW2[128];

    for (int i = threadIdx.x; i < 128 * CL; i += blockDim.x) {
        int c = i >> 7, j = i & 127;          // W1 global is [c][j]
        sW1t[j * CL + c] = W1[i];
    }
    if (threadIdx.x < 128) {
        sb1[threadIdx.x] = b1[threadIdx.x];
        sW2[threadIdx.x] = W2[threadIdx.x];
    }
    __syncthreads();

    int p = blockIdx.x * blockDim.x + threadIdx.x;
    if (p >= P) return;

    float x = __ldg(coords + 3 * p + 0);
    float y = __ldg(coords + 3 * p + 1);
    float z = __ldg(coords + 3 * p + 2);

    int xi, yi, zi; float xf, yf, zf;
    grid_coord(x, xi, xf);
    grid_coord(y, yi, yf);
    grid_coord(z, zi, zf);

    // line rows (layout [n][c])
    const float4* Lx0 = (const float4*)(g_lines[0] + xi * CL);
    const float4* Lx1 = (const float4*)(g_lines[0] + (xi + 1) * CL);
    const float4* Ly0 = (const float4*)(g_lines[1] + yi * CL);
    const float4* Ly1 = (const float4*)(g_lines[1] + (yi + 1) * CL);
    const float4* Lz0 = (const float4*)(g_lines[2] + zi * CL);
    const float4* Lz1 = (const float4*)(g_lines[2] + (zi + 1) * CL);

    // plane bases (layout [h][w][c]); bilerp(plane, gx, gy): gx->w, gy->h
    const float* Pxy = g_planes[0] + ((size_t)yi * NL + xi) * CL;  // h=y, w=x
    const float* Pyz = g_planes[1] + ((size_t)zi * NL + yi) * CL;  // h=z, w=y
    const float* Pxz = g_planes[2] + ((size_t)zi * NL + xi) * CL;  // h=z, w=x

    float wxy00 = (1.f - yf) * (1.f - xf), wxy01 = (1.f - yf) * xf;
    float wxy10 = yf * (1.f - xf),         wxy11 = yf * xf;
    float wyz00 = (1.f - zf) * (1.f - yf), wyz01 = (1.f - zf) * yf;
    float wyz10 = zf * (1.f - yf),         wyz11 = zf * yf;
    float wxz00 = (1.f - zf) * (1.f - xf), wxz01 = (1.f - zf) * xf;
    float wxz10 = zf * (1.f - xf),         wxz11 = zf * xf;

    float feat[CL];
    #pragma unroll
    for (int k = 0; k < 8; k++) {
        int o = k * 4;
        float4 ex  = lerp4(Lx0[k], Lx1[k], xf);
        float4 ey  = lerp4(Ly0[k], Ly1[k], yf);
        float4 ez  = lerp4(Lz0[k], Lz1[k], zf);
        float4 eyz = bil4(Pyz, o, wyz00, wyz01, wyz10, wyz11);
        float4 exz = bil4(Pxz, o, wxz00, wxz01, wxz10, wxz11);
        float4 exy = bil4(Pxy, o, wxy00, wxy01, wxy10, wxy11);
        feat[o + 0] = ex.x * eyz.x + ey.x * exz.x + ez.x * exy.x;
        feat[o + 1] = ex.y * eyz.y + ey.y * exz.y + ez.y * exy.y;
        feat[o + 2] = ex.z * eyz.z + ey.z * exz.z + ez.z * exy.z;
        feat[o + 3] = ex.w * eyz.w + ey.w * exz.w + ez.w * exy.w;
    }

    // MLP: h = relu(feat @ W1 + b1); out = h @ W2 + b2
    float acc = b2[0];
    #pragma unroll 2
    for (int j = 0; j < 128; j += 2) {
        const float4* w0 = (const float4*)(sW1t + j * CL);
        const float4* w1 = (const float4*)(sW1t + (j + 1) * CL);
        float a0 = sb1[j];
        float a1 = sb1[j + 1];
        #pragma unroll
        for (int k = 0; k < 8; k++) {
            float4 q0 = w0[k];
            float4 q1 = w1[k];
            a0 = fmaf(feat[4 * k + 0], q0.x, a0);
            a0 = fmaf(feat[4 * k + 1], q0.y, a0);
            a0 = fmaf(feat[4 * k + 2], q0.z, a0);
            a0 = fmaf(feat[4 * k + 3], q0.w, a0);
            a1 = fmaf(feat[4 * k + 0], q1.x, a1);
            a1 = fmaf(feat[4 * k + 1], q1.y, a1);
            a1 = fmaf(feat[4 * k + 2], q1.z, a1);
            a1 = fmaf(feat[4 * k + 3], q1.w, a1);
        }
        acc = fmaf(fmaxf(a0, 0.0f), sW2[j],     acc);
        acc = fmaf(fmaxf(a1, 0.0f), sW2[j + 1], acc);
    }
    out[p] = acc;
}

// ---------------------------------------------------------------------------
extern "C" void kernel_launch(void* const* d_in, const int* in_sizes, int n_in,
                              void* d_out, int out_size)
{
    const float* coords   = (const float*)d_in[0];
    const float* line_x   = (const float*)d_in[1];
    const float* line_y   = (const float*)d_in[2];
    const float* line_z   = (const float*)d_in[3];
    const float* plane_xy = (const float*)d_in[4];
    const float* plane_yz = (const float*)d_in[5];
    const float* plane_xz = (const float*)d_in[6];
    const float* W1       = (const float*)d_in[7];
    const float* b1       = (const float*)d_in[8];
    const float* W2       = (const float*)d_in[9];
    const float* b2       = (const float*)d_in[10];
    float* out = (float*)d_out;

    int P = in_sizes[0] / 3;

    // Transpose planes (blockIdx.y in [0,NL)) and lines (blockIdx.y == NL).
    dim3 tb(32, 32);
    dim3 tg(NL / 32, NL + 1, 3);
    k_transpose<<<tg, tb>>>(plane_xy, plane_yz, plane_xz, line_x, line_y, line_z);

    int threads = 256;
    int blocks = (P + threads - 1) / threads;
    k_tensorf<<<blocks, threads>>>(coords, W1, b1, W2, b2, out, P);
}

// round 7
// speedup vs baseline: 1.4402x; 1.4402x over previous
#include <cuda_runtime.h>
#include <math.h>

#define NL 512
#define CL 32

typedef unsigned long long u64;

// Scratch: planes transposed to [H][W][C] (channel-contiguous, 128B per texel),
// lines transposed to [N][C].
__device__ float g_planes[3][(size_t)NL * NL * CL];   // 96 MB
__device__ float g_lines[3][NL * CL];

// ---------------------------------------------------------------------------
// Transpose planes [C,H,W] -> [H,W,C] via shared tile (coalesced both sides).
// Also handles lines on blockIdx.y == NL (tail work).
// ---------------------------------------------------------------------------
__global__ void k_transpose(const float* __restrict__ pxy,
                            const float* __restrict__ pyz,
                            const float* __restrict__ pxz,
                            const float* __restrict__ lx,
                            const float* __restrict__ ly,
                            const float* __restrict__ lz)
{
    __shared__ float tile[32][33];
    int plane = blockIdx.z;

    if (blockIdx.y == NL) {
        // lines: [C, NL, 1] -> [NL][C]
        const float* src = (plane == 0) ? lx : (plane == 1) ? ly : lz;
        int n = blockIdx.x * 32 + threadIdx.y;
        int c = threadIdx.x;
        tile[threadIdx.y][threadIdx.x] = src[threadIdx.x * NL + blockIdx.x * 32 + threadIdx.y];
        __syncthreads();
        g_lines[plane][n * CL + c] = tile[threadIdx.y][c];
        return;
    }

    const float* src = (plane == 0) ? pxy : (plane == 1) ? pyz : pxz;
    int h  = blockIdx.y;
    int w0 = blockIdx.x * 32;

    // read: lanes sweep w (coalesced), y sweeps channel
    int wx = threadIdx.x, c_in = threadIdx.y;
    tile[c_in][wx] = src[(size_t)c_in * (NL * NL) + (size_t)h * NL + (w0 + wx)];
    __syncthreads();

    // write: lanes sweep channel (contiguous 128B), y sweeps w
    int c = threadIdx.x, wy = threadIdx.y;
    g_planes[plane][((size_t)h * NL + (w0 + wy)) * CL + c] = tile[c][wy];
}

// ---------------------------------------------------------------------------
// f32x2 packed helpers (Blackwell FFMA2)
// ---------------------------------------------------------------------------
__device__ __forceinline__ u64 pack2(float lo, float hi)
{
    u64 r; asm("mov.b64 %0, {%1, %2};" : "=l"(r) : "f"(lo), "f"(hi)); return r;
}
__device__ __forceinline__ void unpack2(u64 v, float& lo, float& hi)
{
    asm("mov.b64 {%0, %1}, %2;" : "=f"(lo), "=f"(hi) : "l"(v));
}
__device__ __forceinline__ u64 fma2(u64 a, u64 b, u64 c)
{
    u64 d; asm("fma.rn.f32x2 %0, %1, %2, %3;" : "=l"(d) : "l"(a), "l"(b), "l"(c)); return d;
}
__device__ __forceinline__ u64 add2(u64 a, u64 b)
{
    u64 d; asm("add.rn.f32x2 %0, %1, %2;" : "=l"(d) : "l"(a), "l"(b)); return d;
}

// ---------------------------------------------------------------------------
__device__ __forceinline__ void grid_coord(float g, int& i0, float& f)
{
    float ix = (g + 1.0f) * 0.5f * (float)(NL - 1);
    float fl = floorf(ix);
    int   i  = (int)fl;
    float fr = ix - fl;
    if (i < 0)      { i = 0;      fr = 0.0f; }
    if (i > NL - 2) { i = NL - 2; fr = 1.0f; }
    i0 = i; f = fr;
}

// 18 coalesced channel-loads for one point (lane = channel)
__device__ __forceinline__ void gather18(int lane, int xi, int yi, int zi, float* r)
{
    const float* L0 = g_lines[0] + xi * CL + lane;
    const float* L1 = g_lines[1] + yi * CL + lane;
    const float* L2 = g_lines[2] + zi * CL + lane;
    r[0] = L0[0];  r[1] = L0[CL];
    r[2] = L1[0];  r[3] = L1[CL];
    r[4] = L2[0];  r[5] = L2[CL];

    const float* pxy = g_planes[0] + ((size_t)yi * NL + xi) * CL + lane; // h=y,w=x
    const float* pyz = g_planes[1] + ((size_t)zi * NL + yi) * CL + lane; // h=z,w=y
    const float* pxz = g_planes[2] + ((size_t)zi * NL + xi) * CL + lane; // h=z,w=x
    r[6]  = pxy[0];      r[7]  = pxy[CL];
    r[8]  = pxy[NL*CL];  r[9]  = pxy[NL*CL + CL];
    r[10] = pyz[0];      r[11] = pyz[CL];
    r[12] = pyz[NL*CL];  r[13] = pyz[NL*CL + CL];
    r[14] = pxz[0];      r[15] = pxz[CL];
    r[16] = pxz[NL*CL];  r[17] = pxz[NL*CL + CL];
}

__device__ __forceinline__ float interp_feat(const float* r, float xf, float yf, float zf)
{
    float ex = fmaf(xf, r[1] - r[0], r[0]);
    float ey = fmaf(yf, r[3] - r[2], r[2]);
    float ez = fmaf(zf, r[5] - r[4], r[4]);
    // xy plane: inner lerp over w (xf), outer over h (yf)
    float t0 = fmaf(xf, r[7] - r[6], r[6]);
    float t1 = fmaf(xf, r[9] - r[8], r[8]);
    float exy = fmaf(yf, t1 - t0, t0);
    // yz plane: inner yf, outer zf
    float u0 = fmaf(yf, r[11] - r[10], r[10]);
    float u1 = fmaf(yf, r[13] - r[12], r[12]);
    float eyz = fmaf(zf, u1 - u0, u0);
    // xz plane: inner xf, outer zf
    float v0 = fmaf(xf, r[15] - r[14], r[14]);
    float v1 = fmaf(xf, r[17] - r[16], r[16]);
    float exz = fmaf(zf, v1 - v0, v0);
    return ex * eyz + ey * exz + ez * exy;
}

// ---------------------------------------------------------------------------
// Main kernel: warp-cooperative gather (lane=channel) + register-resident MLP.
// Each warp serially processes groups of 32 points (grid-stride over groups).
// Lane j holds W1 columns {j, j+64} and {j+32, j+96} packed as f32x2.
// ---------------------------------------------------------------------------
__global__ __launch_bounds__(128, 2)
void k_tensorf(const float* __restrict__ coords,
               const float* __restrict__ W1,
               const float* __restrict__ b1,
               const float* __restrict__ W2,
               const float* __restrict__ b2,
               float* __restrict__ out, int P)
{
    __shared__ __align__(16) float sFeat[4][2][32];

    const int lane = threadIdx.x & 31;
    const int wib  = threadIdx.x >> 5;
    const int gwarp = blockIdx.x * (blockDim.x >> 5) + wib;
    const int nwarp = gridDim.x * (blockDim.x >> 5);
    const unsigned FULL = 0xffffffffu;

    // Persistent weights: W1 is [CL][128] row-major.
    u64 wA[CL], wB[CL];
    #pragma unroll
    for (int c = 0; c < CL; c++) {
        wA[c] = pack2(__ldg(W1 + c * 128 + lane),      __ldg(W1 + c * 128 + lane + 64));
        wB[c] = pack2(__ldg(W1 + c * 128 + lane + 32), __ldg(W1 + c * 128 + lane + 96));
    }
    const u64 bA = pack2(__ldg(b1 + lane),      __ldg(b1 + lane + 64));
    const u64 bB = pack2(__ldg(b1 + lane + 32), __ldg(b1 + lane + 96));
    const float w2_0 = __ldg(W2 + lane),      w2_1 = __ldg(W2 + lane + 64);
    const float w2_2 = __ldg(W2 + lane + 32), w2_3 = __ldg(W2 + lane + 96);
    const float b2v = __ldg(b2);

    const int ngroups = (P + 31) >> 5;

    for (int g = gwarp; g < ngroups; g += nwarp) {
        const int base = g << 5;
        const int myp  = base + lane;
        const bool valid = myp < P;
        const int pc = valid ? myp : P - 1;

        // Each lane computes its own point's params; broadcast per step.
        float x = coords[3 * pc + 0];
        float y = coords[3 * pc + 1];
        float z = coords[3 * pc + 2];
        int xi, yi, zi; float xf, yf, zf;
        grid_coord(x, xi, xf);
        grid_coord(y, yi, yf);
        grid_coord(z, zi, zf);

        // Prefetch point 0
        float rc[18];
        {
            int bxi = __shfl_sync(FULL, xi, 0);
            int byi = __shfl_sync(FULL, yi, 0);
            int bzi = __shfl_sync(FULL, zi, 0);
            gather18(lane, bxi, byi, bzi, rc);
        }
        float cxf = __shfl_sync(FULL, xf, 0);
        float cyf = __shfl_sync(FULL, yf, 0);
        float czf = __shfl_sync(FULL, zf, 0);

        #pragma unroll 4
        for (int i = 0; i < 32; i++) {
            // Prefetch next point's gathers (hide L2 latency under MLP)
            float rn[18];
            float nxf = 0.f, nyf = 0.f, nzf = 0.f;
            if (i < 31) {
                int nxi = __shfl_sync(FULL, xi, i + 1);
                int nyi = __shfl_sync(FULL, yi, i + 1);
                int nzi = __shfl_sync(FULL, zi, i + 1);
                nxf = __shfl_sync(FULL, xf, i + 1);
                nyf = __shfl_sync(FULL, yf, i + 1);
                nzf = __shfl_sync(FULL, zf, i + 1);
                gather18(lane, nxi, nyi, nzi, rn);
            }

            // Interp current point's channel (this lane = channel)
            float feat = interp_feat(rc, cxf, cyf, czf);

            // Stage features for broadcast (double-buffered row)
            const int buf = i & 1;
            sFeat[wib][buf][lane] = feat;
            __syncwarp();
            const float4* frow = (const float4*)sFeat[wib][buf];

            // MLP: lane j computes h_j, h_{j+32}, h_{j+64}, h_{j+96}
            u64 aA0 = bA, aB0 = bB;
            u64 aA1 = 0ull, aB1 = 0ull;
            #pragma unroll
            for (int cc = 0; cc < 8; cc++) {
                float4 f4 = frow[cc];
                u64 f0 = pack2(f4.x, f4.x);
                u64 f1 = pack2(f4.y, f4.y);
                u64 f2 = pack2(f4.z, f4.z);
                u64 f3 = pack2(f4.w, f4.w);
                int c = cc * 4;
                if (cc & 1) {
                    aA1 = fma2(f0, wA[c + 0], aA1);  aB1 = fma2(f0, wB[c + 0], aB1);
                    aA1 = fma2(f1, wA[c + 1], aA1);  aB1 = fma2(f1, wB[c + 1], aB1);
                    aA1 = fma2(f2, wA[c + 2], aA1);  aB1 = fma2(f2, wB[c + 2], aB1);
                    aA1 = fma2(f3, wA[c + 3], aA1);  aB1 = fma2(f3, wB[c + 3], aB1);
                } else {
                    aA0 = fma2(f0, wA[c + 0], aA0);  aB0 = fma2(f0, wB[c + 0], aB0);
                    aA0 = fma2(f1, wA[c + 1], aA0);  aB0 = fma2(f1, wB[c + 1], aB0);
                    aA0 = fma2(f2, wA[c + 2], aA0);  aB0 = fma2(f2, wB[c + 2], aB0);
                    aA0 = fma2(f3, wA[c + 3], aA0);  aB0 = fma2(f3, wB[c + 3], aB0);
                }
            }
            u64 accA = add2(aA0, aA1);
            u64 accB = add2(aB0, aB1);

            float hA0, hA1, hB0, hB1;
            unpack2(accA, hA0, hA1);
            unpack2(accB, hB0, hB1);
            float s = fmaxf(hA0, 0.f) * w2_0 + fmaxf(hA1, 0.f) * w2_1
                    + fmaxf(hB0, 0.f) * w2_2 + fmaxf(hB1, 0.f) * w2_3;

            // warp sum
            #pragma unroll
            for (int off = 16; off; off >>= 1)
                s += __shfl_xor_sync(FULL, s, off);

            if (lane == i && valid)
                out[myp] = s + b2v;

            // rotate prefetch
            if (i < 31) {
                #pragma unroll
                for (int t = 0; t < 18; t++) rc[t] = rn[t];
                cxf = nxf; cyf = nyf; czf = nzf;
            }
        }
    }
}

// ---------------------------------------------------------------------------
extern "C" void kernel_launch(void* const* d_in, const int* in_sizes, int n_in,
                              void* d_out, int out_size)
{
    const float* coords   = (const float*)d_in[0];
    const float* line_x   = (const float*)d_in[1];
    const float* line_y   = (const float*)d_in[2];
    const float* line_z   = (const float*)d_in[3];
    const float* plane_xy = (const float*)d_in[4];
    const float* plane_yz = (const float*)d_in[5];
    const float* plane_xz = (const float*)d_in[6];
    const float* W1       = (const float*)d_in[7];
    const float* b1       = (const float*)d_in[8];
    const float* W2       = (const float*)d_in[9];
    const float* b2       = (const float*)d_in[10];
    float* out = (float*)d_out;

    int P = in_sizes[0] / 3;

    // Transpose planes (blockIdx.y in [0,NL)) and lines (blockIdx.y == NL).
    dim3 tb(32, 32);
    dim3 tg(NL / 32, NL + 1, 3);
    k_transpose<<<tg, tb>>>(plane_xy, plane_yz, plane_xz, line_x, line_y, line_z);

    // Persistent-ish grid on 152-SM GB300; grid-stride covers the rest.
    int blocks = 304;
    k_tensorf<<<blocks, 128>>>(coords, W1, b1, W2, b2, out, P);
}

// round 10
// speedup vs baseline: 1.5427x; 1.0712x over previous
#include <cuda_runtime.h>
#include <math.h>

#define NL 512
#define CL 32

typedef unsigned long long u64;

// Scratch: planes transposed to [H][W][C] (channel-contiguous, 128B per texel),
// lines transposed to [N][C].
__device__ float g_planes[3][(size_t)NL * NL * CL];   // 96 MB
__device__ float g_lines[3][NL * CL];

// ---------------------------------------------------------------------------
// Transpose planes [C,H,W] -> [H,W,C]. Block (32,16): tile = 32c x 128w.
// grid: (NL/128, NL, 3)
// ---------------------------------------------------------------------------
__global__ void k_transpose_planes(const float* __restrict__ pxy,
                                   const float* __restrict__ pyz,
                                   const float* __restrict__ pxz)
{
    __shared__ float tile[CL][129];
    int plane = blockIdx.z;
    const float* src = (plane == 0) ? pxy : (plane == 1) ? pyz : pxz;
    int h  = blockIdx.y;
    int w0 = blockIdx.x * 128;

    // read: float4, lanes sweep w (512B per row), y sweeps channels
    #pragma unroll
    for (int cy = threadIdx.y; cy < CL; cy += 16) {
        float4 v = *(const float4*)(src + (size_t)cy * (NL * NL) + (size_t)h * NL
                                    + w0 + threadIdx.x * 4);
        tile[cy][threadIdx.x * 4 + 0] = v.x;
        tile[cy][threadIdx.x * 4 + 1] = v.y;
        tile[cy][threadIdx.x * 4 + 2] = v.z;
        tile[cy][threadIdx.x * 4 + 3] = v.w;
    }
    __syncthreads();

    // write: lanes sweep channel (contiguous 128B per texel), y sweeps w
    int c = threadIdx.x;
    #pragma unroll
    for (int w = threadIdx.y; w < 128; w += 16) {
        g_planes[plane][((size_t)h * NL + (w0 + w)) * CL + c] = tile[c][w];
    }
}

__global__ void k_transpose_lines(const float* __restrict__ lx,
                                  const float* __restrict__ ly,
                                  const float* __restrict__ lz)
{
    __shared__ float tile[32][33];
    int plane = blockIdx.z;
    const float* src = (plane == 0) ? lx : (plane == 1) ? ly : lz;
    int n0 = blockIdx.x * 32;
    tile[threadIdx.y][threadIdx.x] = src[threadIdx.x * NL + n0 + threadIdx.y];
    __syncthreads();
    g_lines[plane][(n0 + threadIdx.y) * CL + threadIdx.x] = tile[threadIdx.y][threadIdx.x];
}

// ---------------------------------------------------------------------------
// f32x2 packed helpers (Blackwell FFMA2)
// ---------------------------------------------------------------------------
__device__ __forceinline__ u64 pack2(float lo, float hi)
{
    u64 r; asm("mov.b64 %0, {%1, %2};" : "=l"(r) : "f"(lo), "f"(hi)); return r;
}
__device__ __forceinline__ void unpack2(u64 v, float& lo, float& hi)
{
    asm("mov.b64 {%0, %1}, %2;" : "=f"(lo), "=f"(hi) : "l"(v));
}
__device__ __forceinline__ u64 fma2(u64 a, u64 b, u64 c)
{
    u64 d; asm("fma.rn.f32x2 %0, %1, %2, %3;" : "=l"(d) : "l"(a), "l"(b), "l"(c)); return d;
}

// ---------------------------------------------------------------------------
__device__ __forceinline__ void grid_coord(float g, int& i0, float& f)
{
    float ix = (g + 1.0f) * 0.5f * (float)(NL - 1);
    float fl = floorf(ix);
    int   i  = (int)fl;
    float fr = ix - fl;
    if (i < 0)      { i = 0;      fr = 0.0f; }
    if (i > NL - 2) { i = NL - 2; fr = 1.0f; }
    i0 = i; f = fr;
}

// 18 coalesced channel-loads for one point (lane = channel)
__device__ __forceinline__ void gather18(int lane, int xi, int yi, int zi, float* r)
{
    const float* L0 = g_lines[0] + xi * CL + lane;
    const float* L1 = g_lines[1] + yi * CL + lane;
    const float* L2 = g_lines[2] + zi * CL + lane;
    r[0] = L0[0];  r[1] = L0[CL];
    r[2] = L1[0];  r[3] = L1[CL];
    r[4] = L2[0];  r[5] = L2[CL];

    const float* pxy = g_planes[0] + ((yi * NL + xi) * CL + lane); // h=y,w=x
    const float* pyz = g_planes[1] + ((zi * NL + yi) * CL + lane); // h=z,w=y
    const float* pxz = g_planes[2] + ((zi * NL + xi) * CL + lane); // h=z,w=x
    r[6]  = pxy[0];      r[7]  = pxy[CL];
    r[8]  = pxy[NL*CL];  r[9]  = pxy[NL*CL + CL];
    r[10] = pyz[0];      r[11] = pyz[CL];
    r[12] = pyz[NL*CL];  r[13] = pyz[NL*CL + CL];
    r[14] = pxz[0];      r[15] = pxz[CL];
    r[16] = pxz[NL*CL];  r[17] = pxz[NL*CL + CL];
}

__device__ __forceinline__ float interp_feat(const float* r, float xf, float yf, float zf)
{
    float ex = fmaf(xf, r[1] - r[0], r[0]);
    float ey = fmaf(yf, r[3] - r[2], r[2]);
    float ez = fmaf(zf, r[5] - r[4], r[4]);
    float t0 = fmaf(xf, r[7] - r[6], r[6]);
    float t1 = fmaf(xf, r[9] - r[8], r[8]);
    float exy = fmaf(yf, t1 - t0, t0);
    float u0 = fmaf(yf, r[11] - r[10], r[10]);
    float u1 = fmaf(yf, r[13] - r[12], r[12]);
    float eyz = fmaf(zf, u1 - u0, u0);
    float v0 = fmaf(xf, r[15] - r[14], r[14]);
    float v1 = fmaf(xf, r[17] - r[16], r[16]);
    float exz = fmaf(zf, v1 - v0, v0);
    return ex * eyz + ey * exz + ez * exy;
}

// ---------------------------------------------------------------------------
// Main kernel.
// Phase 1 (lane = channel): warp-cooperative coalesced gather + interp into a
//   padded 32x33 smem feature tile for a 32-point group.
// Phase 2 (lane = point): each lane runs the full MLP for its own point;
//   W1/b1/W2 read from shared as warp-broadcast f32x2 pairs (1 wf each).
// No shuffles, no cross-lane reductions, 3 syncwarps per 32-point group.
// ---------------------------------------------------------------------------
__global__ __launch_bounds__(128, 4)
void k_tensorf(const float* __restrict__ coords,
               const float* __restrict__ W1,
               const float* __restrict__ b1,
               const float* __restrict__ W2,
               const float* __restrict__ b2,
               float* __restrict__ out, int P)
{
    __shared__ __align__(16) u64   sWp[CL * 64];   // [c][pair], pair p=(2p,2p+1)  16KB
    __shared__ __align__(16) u64   sBp[64];
    __shared__ __align__(16) u64   sW2p[64];
    __shared__ __align__(16) float sF[4][32 * 33]; // per-warp feature tile [pt][c]
    __shared__ __align__(16) float4 sPf[4][32];
    __shared__ __align__(16) int4   sPi[4][32];

    const int tid = threadIdx.x;

    // Stage weights as f32x2 pairs (once per block).
    for (int idx = tid; idx < CL * 64; idx += 128) {
        int c = idx >> 6, p = idx & 63;
        sWp[idx] = pack2(W1[c * 128 + 2 * p], W1[c * 128 + 2 * p + 1]);
    }
    if (tid < 64) {
        sBp[tid]  = pack2(b1[2 * tid], b1[2 * tid + 1]);
        sW2p[tid] = pack2(W2[2 * tid], W2[2 * tid + 1]);
    }
    __syncthreads();

    const int lane  = tid & 31;
    const int wib   = tid >> 5;
    const int gwarp = blockIdx.x * 4 + wib;
    const int nwarp = gridDim.x * 4;
    float* myF = sF[wib];
    const float b2v = __ldg(b2);

    const int ngroups = (P + 31) >> 5;

    for (int g = gwarp; g < ngroups; g += nwarp) {
        const int base = g << 5;
        const int myp  = base + lane;
        const bool valid = myp < P;
        const int pc = valid ? myp : P - 1;

        float x = coords[3 * pc + 0];
        float y = coords[3 * pc + 1];
        float z = coords[3 * pc + 2];
        int xi, yi, zi; float xf, yf, zf;
        grid_coord(x, xi, xf);
        grid_coord(y, yi, yf);
        grid_coord(z, zi, zf);
        sPf[wib][lane] = make_float4(xf, yf, zf, 0.f);
        sPi[wib][lane] = make_int4(xi, yi, zi, 0);
        __syncwarp();

        // ---- Phase 1: gather + interp (software-pipelined by one point) ----
        float rc[18];
        int4   pi = sPi[wib][0];
        float4 pf = sPf[wib][0];
        gather18(lane, pi.x, pi.y, pi.z, rc);

        #pragma unroll 2
        for (int i = 0; i < 32; i++) {
            float rn[18]; int4 ni; float4 nf;
            if (i < 31) {
                ni = sPi[wib][i + 1];
                nf = sPf[wib][i + 1];
                gather18(lane, ni.x, ni.y, ni.z, rn);
            }
            myF[i * 33 + lane] = interp_feat(rc, pf.x, pf.y, pf.z);
            if (i < 31) {
                #pragma unroll
                for (int t = 0; t < 18; t++) rc[t] = rn[t];
                pi = ni; pf = nf;
            }
        }
        __syncwarp();

        // ---- Phase 2: lane = point, full MLP per lane ----
        // Feature reads: row `lane`, stride 33 -> (lane+c)%32 banks, conflict-free.
        u64 fp[CL];
        #pragma unroll
        for (int c = 0; c < CL; c++) {
            float fv = myF[lane * 33 + c];
            fp[c] = pack2(fv, fv);
        }

        float s = b2v;
        #pragma unroll 1
        for (int ch = 0; ch < 8; ch++) {      // 16 hidden units per chunk
            u64 acc[8];
            #pragma unroll
            for (int k = 0; k < 8; k++) acc[k] = sBp[ch * 8 + k];

            #pragma unroll 4
            for (int c = 0; c < CL; c++) {
                const u64* w = &sWp[c * 64 + ch * 8];  // broadcast LDS.128 x4
                #pragma unroll
                for (int k = 0; k < 8; k++) acc[k] = fma2(fp[c], w[k], acc[k]);
            }

            #pragma unroll
            for (int k = 0; k < 8; k++) {
                float h0, h1, w20, w21;
                unpack2(acc[k], h0, h1);
                unpack2(sW2p[ch * 8 + k], w20, w21);
                s = fmaf(fmaxf(h0, 0.f), w20, s);
                s = fmaf(fmaxf(h1, 0.f), w21, s);
            }
        }

        if (valid) out[myp] = s;
        __syncwarp();   // protect sP/sF before next group's writes
    }
}

// ---------------------------------------------------------------------------
extern "C" void kernel_launch(void* const* d_in, const int* in_sizes, int n_in,
                              void* d_out, int out_size)
{
    const float* coords   = (const float*)d_in[0];
    const float* line_x   = (const float*)d_in[1];
    const float* line_y   = (const float*)d_in[2];
    const float* line_z   = (const float*)d_in[3];
    const float* plane_xy = (const float*)d_in[4];
    const float* plane_yz = (const float*)d_in[5];
    const float* plane_xz = (const float*)d_in[6];
    const float* W1       = (const float*)d_in[7];
    const float* b1       = (const float*)d_in[8];
    const float* W2       = (const float*)d_in[9];
    const float* b2       = (const float*)d_in[10];
    float* out = (float*)d_out;

    int P = in_sizes[0] / 3;

    k_transpose_planes<<<dim3(NL / 128, NL, 3), dim3(32, 16)>>>(plane_xy, plane_yz, plane_xz);
    k_transpose_lines<<<dim3(NL / 32, 1, 3), dim3(32, 32)>>>(line_x, line_y, line_z);

    // Persistent grid-stride over 32-point groups (4 blocks/SM on 152 SMs).
    int blocks = 608;
    k_tensorf<<<blocks, 128>>>(coords, W1, b1, W2, b2, out, P);
}

// round 11
// speedup vs baseline: 1.7842x; 1.1565x over previous
#include <cuda_runtime.h>
#include <math.h>

#define NL 512
#define CL 32

typedef unsigned long long u64;

// Scratch: planes transposed to [H][W][C] (channel-contiguous, 128B per texel),
// lines transposed to [N][C].
__device__ float g_planes[3][(size_t)NL * NL * CL];   // 96 MB
__device__ float g_lines[3][NL * CL];

// ---------------------------------------------------------------------------
// Transpose planes [C,H,W] -> [H,W,C]. Block (32,16): tile = 32c x 128w.
// grid: (NL/128, NL, 3)
// ---------------------------------------------------------------------------
__global__ void k_transpose_planes(const float* __restrict__ pxy,
                                   const float* __restrict__ pyz,
                                   const float* __restrict__ pxz)
{
    __shared__ float tile[CL][129];
    int plane = blockIdx.z;
    const float* src = (plane == 0) ? pxy : (plane == 1) ? pyz : pxz;
    int h  = blockIdx.y;
    int w0 = blockIdx.x * 128;

    #pragma unroll
    for (int cy = threadIdx.y; cy < CL; cy += 16) {
        float4 v = *(const float4*)(src + (size_t)cy * (NL * NL) + (size_t)h * NL
                                    + w0 + threadIdx.x * 4);
        tile[cy][threadIdx.x * 4 + 0] = v.x;
        tile[cy][threadIdx.x * 4 + 1] = v.y;
        tile[cy][threadIdx.x * 4 + 2] = v.z;
        tile[cy][threadIdx.x * 4 + 3] = v.w;
    }
    __syncthreads();

    int c = threadIdx.x;
    #pragma unroll
    for (int w = threadIdx.y; w < 128; w += 16) {
        g_planes[plane][((size_t)h * NL + (w0 + w)) * CL + c] = tile[c][w];
    }
}

__global__ void k_transpose_lines(const float* __restrict__ lx,
                                  const float* __restrict__ ly,
                                  const float* __restrict__ lz)
{
    __shared__ float tile[32][33];
    int plane = blockIdx.z;
    const float* src = (plane == 0) ? lx : (plane == 1) ? ly : lz;
    int n0 = blockIdx.x * 32;
    tile[threadIdx.y][threadIdx.x] = src[threadIdx.x * NL + n0 + threadIdx.y];
    __syncthreads();
    g_lines[plane][(n0 + threadIdx.y) * CL + threadIdx.x] = tile[threadIdx.y][threadIdx.x];
}

// ---------------------------------------------------------------------------
// f32x2 packed helpers (Blackwell FFMA2)
// ---------------------------------------------------------------------------
__device__ __forceinline__ u64 pack2(float lo, float hi)
{
    u64 r; asm("mov.b64 %0, {%1, %2};" : "=l"(r) : "f"(lo), "f"(hi)); return r;
}
__device__ __forceinline__ void unpack2(u64 v, float& lo, float& hi)
{
    asm("mov.b64 {%0, %1}, %2;" : "=f"(lo), "=f"(hi) : "l"(v));
}
__device__ __forceinline__ u64 fma2(u64 a, u64 b, u64 c)
{
    u64 d; asm("fma.rn.f32x2 %0, %1, %2, %3;" : "=l"(d) : "l"(a), "l"(b), "l"(c)); return d;
}

// ---------------------------------------------------------------------------
__device__ __forceinline__ void grid_coord(float g, int& i0, float& f)
{
    float ix = (g + 1.0f) * 0.5f * (float)(NL - 1);
    float fl = floorf(ix);
    int   i  = (int)fl;
    float fr = ix - fl;
    if (i < 0)      { i = 0;      fr = 0.0f; }
    if (i > NL - 2) { i = NL - 2; fr = 1.0f; }
    i0 = i; f = fr;
}

// 18 coalesced channel-loads for one point (lane = channel)
__device__ __forceinline__ void gather18(int lane, int xi, int yi, int zi, float* r)
{
    const float* L0 = g_lines[0] + xi * CL + lane;
    const float* L1 = g_lines[1] + yi * CL + lane;
    const float* L2 = g_lines[2] + zi * CL + lane;
    r[0] = L0[0];  r[1] = L0[CL];
    r[2] = L1[0];  r[3] = L1[CL];
    r[4] = L2[0];  r[5] = L2[CL];

    const float* pxy = g_planes[0] + ((yi * NL + xi) * CL + lane); // h=y,w=x
    const float* pyz = g_planes[1] + ((zi * NL + yi) * CL + lane); // h=z,w=y
    const float* pxz = g_planes[2] + ((zi * NL + xi) * CL + lane); // h=z,w=x
    r[6]  = pxy[0];      r[7]  = pxy[CL];
    r[8]  = pxy[NL*CL];  r[9]  = pxy[NL*CL + CL];
    r[10] = pyz[0];      r[11] = pyz[CL];
    r[12] = pyz[NL*CL];  r[13] = pyz[NL*CL + CL];
    r[14] = pxz[0];      r[15] = pxz[CL];
    r[16] = pxz[NL*CL];  r[17] = pxz[NL*CL + CL];
}

__device__ __forceinline__ float interp_feat(const float* r, float xf, float yf, float zf)
{
    float ex = fmaf(xf, r[1] - r[0], r[0]);
    float ey = fmaf(yf, r[3] - r[2], r[2]);
    float ez = fmaf(zf, r[5] - r[4], r[4]);
    float t0 = fmaf(xf, r[7] - r[6], r[6]);
    float t1 = fmaf(xf, r[9] - r[8], r[8]);
    float exy = fmaf(yf, t1 - t0, t0);
    float u0 = fmaf(yf, r[11] - r[10], r[10]);
    float u1 = fmaf(yf, r[13] - r[12], r[12]);
    float eyz = fmaf(zf, u1 - u0, u0);
    float v0 = fmaf(xf, r[15] - r[14], r[14]);
    float v1 = fmaf(xf, r[17] - r[16], r[16]);
    float exz = fmaf(zf, v1 - v0, v0);
    return ex * eyz + ey * exz + ez * exy;
}

// ---------------------------------------------------------------------------
// Main kernel.
// Phase 1 (lane = channel): warp-cooperative coalesced gather + interp into a
//   padded 32x33 smem feature tile; explicit double-buffer (no register copies).
// Phase 2 (lane = point): full MLP per lane in 4 chunks of 32 hidden units;
//   features re-read from smem per chunk (no big live register array);
//   W1/b1/W2 read from shared as warp-broadcast f32x2 pairs.
// ---------------------------------------------------------------------------
__global__ __launch_bounds__(128, 6)
void k_tensorf(const float* __restrict__ coords,
               const float* __restrict__ W1,
               const float* __restrict__ b1,
               const float* __restrict__ W2,
               const float* __restrict__ b2,
               float* __restrict__ out, int P)
{
    __shared__ __align__(16) u64   sWp[CL * 64];   // [c][pair]  16KB
    __shared__ __align__(16) u64   sBp[64];
    __shared__ __align__(16) u64   sW2p[64];
    __shared__ __align__(16) float sF[4][32 * 33]; // per-warp feature tile [pt][c]
    __shared__ __align__(16) float4 sPf[4][32];
    __shared__ __align__(16) int4   sPi[4][32];

    const int tid = threadIdx.x;

    // Stage weights as f32x2 pairs (once per block).
    for (int idx = tid; idx < CL * 64; idx += 128) {
        int c = idx >> 6, p = idx & 63;
        sWp[idx] = pack2(W1[c * 128 + 2 * p], W1[c * 128 + 2 * p + 1]);
    }
    if (tid < 64) {
        sBp[tid]  = pack2(b1[2 * tid], b1[2 * tid + 1]);
        sW2p[tid] = pack2(W2[2 * tid], W2[2 * tid + 1]);
    }
    __syncthreads();

    const int lane  = tid & 31;
    const int wib   = tid >> 5;
    const int gwarp = blockIdx.x * 4 + wib;
    const int nwarp = gridDim.x * 4;
    float* myF = sF[wib];
    const float b2v = __ldg(b2);

    const int ngroups = (P + 31) >> 5;

    for (int g = gwarp; g < ngroups; g += nwarp) {
        const int base = g << 5;
        const int myp  = base + lane;
        const bool valid = myp < P;
        const int pc = valid ? myp : P - 1;

        float x = coords[3 * pc + 0];
        float y = coords[3 * pc + 1];
        float z = coords[3 * pc + 2];
        int xi, yi, zi; float xf, yf, zf;
        grid_coord(x, xi, xf);
        grid_coord(y, yi, yf);
        grid_coord(z, zi, zf);
        sPf[wib][lane] = make_float4(xf, yf, zf, 0.f);
        sPi[wib][lane] = make_int4(xi, yi, zi, 0);
        __syncwarp();

        // ---- Phase 1: gather + interp, explicit double buffer ----
        float r0[18], r1[18];
        int4   ia = sPi[wib][0];
        float4 fa = sPf[wib][0];
        gather18(lane, ia.x, ia.y, ia.z, r0);

        #pragma unroll 1
        for (int i = 0; i < 32; i += 2) {
            int4   ib = sPi[wib][i + 1];
            float4 fb = sPf[wib][i + 1];
            gather18(lane, ib.x, ib.y, ib.z, r1);
            myF[i * 33 + lane] = interp_feat(r0, fa.x, fa.y, fa.z);
            if (i + 2 < 32) {
                ia = sPi[wib][i + 2];
                fa = sPf[wib][i + 2];
                gather18(lane, ia.x, ia.y, ia.z, r0);
            }
            myF[(i + 1) * 33 + lane] = interp_feat(r1, fb.x, fb.y, fb.z);
        }
        __syncwarp();

        // ---- Phase 2: lane = point, MLP in 4 chunks of 16 pairs ----
        float s = b2v;
        #pragma unroll 1
        for (int ch = 0; ch < 4; ch++) {
            u64 acc[16];
            #pragma unroll
            for (int k = 0; k < 16; k++) acc[k] = sBp[ch * 16 + k];

            #pragma unroll 4
            for (int c = 0; c < CL; c++) {
                float fv = myF[lane * 33 + c];           // conflict-free rotation
                u64 f2 = pack2(fv, fv);
                const u64* w = &sWp[c * 64 + ch * 16];   // broadcast LDS.128 x8
                #pragma unroll
                for (int k = 0; k < 16; k++) acc[k] = fma2(f2, w[k], acc[k]);
            }

            #pragma unroll
            for (int k = 0; k < 16; k++) {
                float h0, h1, w20, w21;
                unpack2(acc[k], h0, h1);
                unpack2(sW2p[ch * 16 + k], w20, w21);
                s = fmaf(fmaxf(h0, 0.f), w20, s);
                s = fmaf(fmaxf(h1, 0.f), w21, s);
            }
        }

        if (valid) out[myp] = s;
        __syncwarp();   // protect sP/sF before next group's writes
    }
}

// ---------------------------------------------------------------------------
extern "C" void kernel_launch(void* const* d_in, const int* in_sizes, int n_in,
                              void* d_out, int out_size)
{
    const float* coords   = (const float*)d_in[0];
    const float* line_x   = (const float*)d_in[1];
    const float* line_y   = (const float*)d_in[2];
    const float* line_z   = (const float*)d_in[3];
    const float* plane_xy = (const float*)d_in[4];
    const float* plane_yz = (const float*)d_in[5];
    const float* plane_xz = (const float*)d_in[6];
    const float* W1       = (const float*)d_in[7];
    const float* b1       = (const float*)d_in[8];
    const float* W2       = (const float*)d_in[9];
    const float* b2       = (const float*)d_in[10];
    float* out = (float*)d_out;

    int P = in_sizes[0] / 3;

    k_transpose_planes<<<dim3(NL / 128, NL, 3), dim3(32, 16)>>>(plane_xy, plane_yz, plane_xz);
    k_transpose_lines<<<dim3(NL / 32, 1, 3), dim3(32, 32)>>>(line_x, line_y, line_z);

    // Persistent grid-stride over 32-point groups (6 blocks/SM on 152 SMs).
    int blocks = 912;
    k_tensorf<<<blocks, 128>>>(coords, W1, b1, W2, b2, out, P);
}

// round 12
// speedup vs baseline: 2.1104x; 1.1828x over previous
#include <cuda_runtime.h>
#include <math.h>

#define NL 512
#define CL 32

typedef unsigned long long u64;

// Scratch: planes transposed to [H][W][C] (channel-contiguous, 128B per texel),
// lines transposed to [N][C].
__device__ float g_planes[3][(size_t)NL * NL * CL];   // 96 MB
__device__ float g_lines[3][NL * CL];

// ---------------------------------------------------------------------------
// Transpose planes [C,H,W] -> [H,W,C]. Block (32,16): tile = 32c x 128w.
// ---------------------------------------------------------------------------
__global__ void k_transpose_planes(const float* __restrict__ pxy,
                                   const float* __restrict__ pyz,
                                   const float* __restrict__ pxz)
{
    __shared__ float tile[CL][129];
    int plane = blockIdx.z;
    const float* src = (plane == 0) ? pxy : (plane == 1) ? pyz : pxz;
    int h  = blockIdx.y;
    int w0 = blockIdx.x * 128;

    #pragma unroll
    for (int cy = threadIdx.y; cy < CL; cy += 16) {
        float4 v = *(const float4*)(src + (size_t)cy * (NL * NL) + (size_t)h * NL
                                    + w0 + threadIdx.x * 4);
        tile[cy][threadIdx.x * 4 + 0] = v.x;
        tile[cy][threadIdx.x * 4 + 1] = v.y;
        tile[cy][threadIdx.x * 4 + 2] = v.z;
        tile[cy][threadIdx.x * 4 + 3] = v.w;
    }
    __syncthreads();

    int c = threadIdx.x;
    #pragma unroll
    for (int w = threadIdx.y; w < 128; w += 16) {
        g_planes[plane][((size_t)h * NL + (w0 + w)) * CL + c] = tile[c][w];
    }
}

__global__ void k_transpose_lines(const float* __restrict__ lx,
                                  const float* __restrict__ ly,
                                  const float* __restrict__ lz)
{
    __shared__ float tile[32][33];
    int plane = blockIdx.z;
    const float* src = (plane == 0) ? lx : (plane == 1) ? ly : lz;
    int n0 = blockIdx.x * 32;
    tile[threadIdx.y][threadIdx.x] = src[threadIdx.x * NL + n0 + threadIdx.y];
    __syncthreads();
    g_lines[plane][(n0 + threadIdx.y) * CL + threadIdx.x] = tile[threadIdx.y][threadIdx.x];
}

// ---------------------------------------------------------------------------
// f32x2 packed helpers (Blackwell FFMA2)
// ---------------------------------------------------------------------------
__device__ __forceinline__ u64 pack2(float lo, float hi)
{
    u64 r; asm("mov.b64 %0, {%1, %2};" : "=l"(r) : "f"(lo), "f"(hi)); return r;
}
__device__ __forceinline__ void unpack2(u64 v, float& lo, float& hi)
{
    asm("mov.b64 {%0, %1}, %2;" : "=f"(lo), "=f"(hi) : "l"(v));
}
__device__ __forceinline__ u64 fma2(u64 a, u64 b, u64 c)
{
    u64 d; asm("fma.rn.f32x2 %0, %1, %2, %3;" : "=l"(d) : "l"(a), "l"(b), "l"(c)); return d;
}

// ---------------------------------------------------------------------------
__device__ __forceinline__ void grid_coord(float g, int& i0, float& f)
{
    float ix = (g + 1.0f) * 0.5f * (float)(NL - 1);
    float fl = floorf(ix);
    int   i  = (int)fl;
    float fr = ix - fl;
    if (i < 0)      { i = 0;      fr = 0.0f; }
    if (i > NL - 2) { i = NL - 2; fr = 1.0f; }
    i0 = i; f = fr;
}

// 18 coalesced channel-loads for one point (lane = channel)
__device__ __forceinline__ void gather18(int lane, int xi, int yi, int zi, float* r)
{
    const float* L0 = g_lines[0] + xi * CL + lane;
    const float* L1 = g_lines[1] + yi * CL + lane;
    const float* L2 = g_lines[2] + zi * CL + lane;
    r[0] = L0[0];  r[1] = L0[CL];
    r[2] = L1[0];  r[3] = L1[CL];
    r[4] = L2[0];  r[5] = L2[CL];

    const float* pxy = g_planes[0] + ((yi * NL + xi) * CL + lane); // h=y,w=x
    const float* pyz = g_planes[1] + ((zi * NL + yi) * CL + lane); // h=z,w=y
    const float* pxz = g_planes[2] + ((zi * NL + xi) * CL + lane); // h=z,w=x
    r[6]  = pxy[0];      r[7]  = pxy[CL];
    r[8]  = pxy[NL*CL];  r[9]  = pxy[NL*CL + CL];
    r[10] = pyz[0];      r[11] = pyz[CL];
    r[12] = pyz[NL*CL];  r[13] = pyz[NL*CL + CL];
    r[14] = pxz[0];      r[15] = pxz[CL];
    r[16] = pxz[NL*CL];  r[17] = pxz[NL*CL + CL];
}

__device__ __forceinline__ float interp_feat(const float* r, float xf, float yf, float zf)
{
    float ex = fmaf(xf, r[1] - r[0], r[0]);
    float ey = fmaf(yf, r[3] - r[2], r[2]);
    float ez = fmaf(zf, r[5] - r[4], r[4]);
    float t0 = fmaf(xf, r[7] - r[6], r[6]);
    float t1 = fmaf(xf, r[9] - r[8], r[8]);
    float exy = fmaf(yf, t1 - t0, t0);
    float u0 = fmaf(yf, r[11] - r[10], r[10]);
    float u1 = fmaf(yf, r[13] - r[12], r[12]);
    float eyz = fmaf(zf, u1 - u0, u0);
    float v0 = fmaf(xf, r[15] - r[14], r[14]);
    float v1 = fmaf(xf, r[17] - r[16], r[16]);
    float exz = fmaf(zf, v1 - v0, v0);
    return ex * eyz + ey * exz + ez * exy;
}

// ---------------------------------------------------------------------------
// Main kernel.
// Phase 1 (lane = channel): warp-cooperative coalesced gather + interp, with a
//   4-deep software pipeline (gathers issued ~3 iterations before consumption
//   to cover L2 hit latency).
// Phase 2 (lane = point): full MLP per lane in 4 chunks of 32 hidden units;
//   W1/b1/W2 read from shared as warp-broadcast f32x2 pairs.
// ---------------------------------------------------------------------------
__global__ __launch_bounds__(128, 5)
void k_tensorf(const float* __restrict__ coords,
               const float* __restrict__ W1,
               const float* __restrict__ b1,
               const float* __restrict__ W2,
               const float* __restrict__ b2,
               float* __restrict__ out, int P)
{
    __shared__ __align__(16) u64   sWp[CL * 64];   // [c][pair]  16KB
    __shared__ __align__(16) u64   sBp[64];
    __shared__ __align__(16) u64   sW2p[64];
    __shared__ __align__(16) float sF[4][32 * 33]; // per-warp feature tile [pt][c]
    __shared__ __align__(16) float4 sPf[4][32];
    __shared__ __align__(16) int4   sPi[4][32];

    const int tid = threadIdx.x;

    // Stage weights as f32x2 pairs (once per block).
    for (int idx = tid; idx < CL * 64; idx += 128) {
        int c = idx >> 6, p = idx & 63;
        sWp[idx] = pack2(W1[c * 128 + 2 * p], W1[c * 128 + 2 * p + 1]);
    }
    if (tid < 64) {
        sBp[tid]  = pack2(b1[2 * tid], b1[2 * tid + 1]);
        sW2p[tid] = pack2(W2[2 * tid], W2[2 * tid + 1]);
    }
    __syncthreads();

    const int lane  = tid & 31;
    const int wib   = tid >> 5;
    const int gwarp = blockIdx.x * 4 + wib;
    const int nwarp = gridDim.x * 4;
    float* myF = sF[wib];
    const float b2v = __ldg(b2);

    const int ngroups = (P + 31) >> 5;

    for (int g = gwarp; g < ngroups; g += nwarp) {
        const int base = g << 5;
        const int myp  = base + lane;
        const bool valid = myp < P;
        const int pc = valid ? myp : P - 1;

        float x = __ldg(coords + 3 * pc + 0);
        float y = __ldg(coords + 3 * pc + 1);
        float z = __ldg(coords + 3 * pc + 2);
        int xi, yi, zi; float xf, yf, zf;
        grid_coord(x, xi, xf);
        grid_coord(y, yi, yf);
        grid_coord(z, zi, zf);
        sPf[wib][lane] = make_float4(xf, yf, zf, 0.f);
        sPi[wib][lane] = make_int4(xi, yi, zi, 0);
        __syncwarp();

        // ---- Phase 1: gather + interp, 4-deep ring pipeline ----
        float rb[4][18];
        {
            int4 i0 = sPi[wib][0], i1 = sPi[wib][1], i2 = sPi[wib][2], i3 = sPi[wib][3];
            gather18(lane, i0.x, i0.y, i0.z, rb[0]);
            gather18(lane, i1.x, i1.y, i1.z, rb[1]);
            gather18(lane, i2.x, i2.y, i2.z, rb[2]);
            gather18(lane, i3.x, i3.y, i3.z, rb[3]);
        }

        #pragma unroll 1
        for (int i = 0; i < 32; i += 4) {
            #pragma unroll
            for (int k = 0; k < 4; k++) {
                int pi = i + k;
                float4 pf = sPf[wib][pi];
                float feat = interp_feat(rb[k], pf.x, pf.y, pf.z);
                myF[pi * 33 + lane] = feat;
                int np = pi + 4;
                if (np < 32) {
                    int4 ni = sPi[wib][np];
                    gather18(lane, ni.x, ni.y, ni.z, rb[k]);
                }
            }
        }
        __syncwarp();

        // ---- Phase 2: lane = point, MLP in 4 chunks of 16 pairs ----
        float s = b2v;
        #pragma unroll 1
        for (int ch = 0; ch < 4; ch++) {
            u64 acc[16];
            #pragma unroll
            for (int k = 0; k < 16; k++) acc[k] = sBp[ch * 16 + k];

            #pragma unroll 4
            for (int c = 0; c < CL; c++) {
                float fv = myF[lane * 33 + c];           // conflict-free rotation
                u64 f2 = pack2(fv, fv);
                const u64* w = &sWp[c * 64 + ch * 16];   // broadcast LDS.128 x8
                #pragma unroll
                for (int k = 0; k < 16; k++) acc[k] = fma2(f2, w[k], acc[k]);
            }

            #pragma unroll
            for (int k = 0; k < 16; k++) {
                float h0, h1, w20, w21;
                unpack2(acc[k], h0, h1);
                unpack2(sW2p[ch * 16 + k], w20, w21);
                s = fmaf(fmaxf(h0, 0.f), w20, s);
                s = fmaf(fmaxf(h1, 0.f), w21, s);
            }
        }

        if (valid) out[myp] = s;
        __syncwarp();   // protect sP/sF before next group's writes
    }
}

// ---------------------------------------------------------------------------
extern "C" void kernel_launch(void* const* d_in, const int* in_sizes, int n_in,
                              void* d_out, int out_size)
{
    const float* coords   = (const float*)d_in[0];
    const float* line_x   = (const float*)d_in[1];
    const float* line_y   = (const float*)d_in[2];
    const float* line_z   = (const float*)d_in[3];
    const float* plane_xy = (const float*)d_in[4];
    const float* plane_yz = (const float*)d_in[5];
    const float* plane_xz = (const float*)d_in[6];
    const float* W1       = (const float*)d_in[7];
    const float* b1       = (const float*)d_in[8];
    const float* W2       = (const float*)d_in[9];
    const float* b2       = (const float*)d_in[10];
    float* out = (float*)d_out;

    int P = in_sizes[0] / 3;

    k_transpose_planes<<<dim3(NL / 128, NL, 3), dim3(32, 16)>>>(plane_xy, plane_yz, plane_xz);
    k_transpose_lines<<<dim3(NL / 32, 1, 3), dim3(32, 32)>>>(line_x, line_y, line_z);

    // Persistent grid-stride over 32-point groups (5 blocks/SM on 152 SMs).
    int blocks = 760;
    k_tensorf<<<blocks, 128>>>(coords, W1, b1, W2, b2, out, P);
}

// round 16
// speedup vs baseline: 2.8958x; 1.3722x over previous
#include <cuda_runtime.h>
#include <cuda_bf16.h>
#include <math.h>
#include <cstdint>

#define NL 512
#define CL 32

// Scratch: planes transposed to [H][W][C] (channel-contiguous), lines [N][C].
__device__ float g_planes[3][(size_t)NL * NL * CL];   // 96 MB
__device__ float g_lines[3][NL * CL];

// ---------------------------------------------------------------------------
// Transposes (unchanged, measured ~39us total)
// ---------------------------------------------------------------------------
__global__ void k_transpose_planes(const float* __restrict__ pxy,
                                   const float* __restrict__ pyz,
                                   const float* __restrict__ pxz)
{
    __shared__ float tile[CL][129];
    int plane = blockIdx.z;
    const float* src = (plane == 0) ? pxy : (plane == 1) ? pyz : pxz;
    int h  = blockIdx.y;
    int w0 = blockIdx.x * 128;

    #pragma unroll
    for (int cy = threadIdx.y; cy < CL; cy += 16) {
        float4 v = *(const float4*)(src + (size_t)cy * (NL * NL) + (size_t)h * NL
                                    + w0 + threadIdx.x * 4);
        tile[cy][threadIdx.x * 4 + 0] = v.x;
        tile[cy][threadIdx.x * 4 + 1] = v.y;
        tile[cy][threadIdx.x * 4 + 2] = v.z;
        tile[cy][threadIdx.x * 4 + 3] = v.w;
    }
    __syncthreads();

    int c = threadIdx.x;
    #pragma unroll
    for (int w = threadIdx.y; w < 128; w += 16) {
        g_planes[plane][((size_t)h * NL + (w0 + w)) * CL + c] = tile[c][w];
    }
}

__global__ void k_transpose_lines(const float* __restrict__ lx,
                                  const float* __restrict__ ly,
                                  const float* __restrict__ lz)
{
    __shared__ float tile[32][33];
    int plane = blockIdx.z;
    const float* src = (plane == 0) ? lx : (plane == 1) ? ly : lz;
    int n0 = blockIdx.x * 32;
    tile[threadIdx.y][threadIdx.x] = src[threadIdx.x * NL + n0 + threadIdx.y];
    __syncthreads();
    g_lines[plane][(n0 + threadIdx.y) * CL + threadIdx.x] = tile[threadIdx.y][threadIdx.x];
}

// ---------------------------------------------------------------------------
// mma.sync / ldmatrix helpers (sm_80+ features; legal on plain sm_103 target)
// ---------------------------------------------------------------------------
__device__ __forceinline__ uint32_t smem_to_u32(const void* p) {
    uint32_t a;
    asm("{ .reg .u64 t; cvta.to.shared.u64 t, %1; cvt.u32.u64 %0, t; }"
        : "=r"(a) : "l"(p));
    return a;
}

__device__ __forceinline__ void ldsm_x4(uint32_t& r0, uint32_t& r1,
                                        uint32_t& r2, uint32_t& r3, uint32_t addr)
{
    asm volatile("ldmatrix.sync.aligned.m8n8.x4.shared.b16 {%0,%1,%2,%3}, [%4];"
                 : "=r"(r0), "=r"(r1), "=r"(r2), "=r"(r3) : "r"(addr));
}

__device__ __forceinline__ void mma_bf16(float& c0, float& c1, float& c2, float& c3,
                                         uint32_t a0, uint32_t a1, uint32_t a2, uint32_t a3,
                                         uint32_t b0, uint32_t b1)
{
    asm volatile("mma.sync.aligned.m16n8k16.row.col.f32.bf16.bf16.f32 "
                 "{%0,%1,%2,%3}, {%4,%5,%6,%7}, {%8,%9}, {%0,%1,%2,%3};"
                 : "+f"(c0), "+f"(c1), "+f"(c2), "+f"(c3)
                 : "r"(a0), "r"(a1), "r"(a2), "r"(a3), "r"(b0), "r"(b1));
}

// ---------------------------------------------------------------------------
__device__ __forceinline__ void grid_coord(float g, int& i0, float& f)
{
    float ix = (g + 1.0f) * 0.5f * (float)(NL - 1);
    float fl = floorf(ix);
    int   i  = (int)fl;
    float fr = ix - fl;
    if (i < 0)      { i = 0;      fr = 0.0f; }
    if (i > NL - 2) { i = NL - 2; fr = 1.0f; }
    i0 = i; f = fr;
}

// 18 coalesced channel-loads for one point (lane = channel)
__device__ __forceinline__ void gather18(int lane, int xi, int yi, int zi, float* r)
{
    const float* L0 = g_lines[0] + xi * CL + lane;
    const float* L1 = g_lines[1] + yi * CL + lane;
    const float* L2 = g_lines[2] + zi * CL + lane;
    r[0] = L0[0];  r[1] = L0[CL];
    r[2] = L1[0];  r[3] = L1[CL];
    r[4] = L2[0];  r[5] = L2[CL];

    const float* pxy = g_planes[0] + ((yi * NL + xi) * CL + lane); // h=y,w=x
    const float* pyz = g_planes[1] + ((zi * NL + yi) * CL + lane); // h=z,w=y
    const float* pxz = g_planes[2] + ((zi * NL + xi) * CL + lane); // h=z,w=x
    r[6]  = pxy[0];      r[7]  = pxy[CL];
    r[8]  = pxy[NL*CL];  r[9]  = pxy[NL*CL + CL];
    r[10] = pyz[0];      r[11] = pyz[CL];
    r[12] = pyz[NL*CL];  r[13] = pyz[NL*CL + CL];
    r[14] = pxz[0];      r[15] = pxz[CL];
    r[16] = pxz[NL*CL];  r[17] = pxz[NL*CL + CL];
}

__device__ __forceinline__ float interp_feat(const float* r, float xf, float yf, float zf)
{
    float ex = fmaf(xf, r[1] - r[0], r[0]);
    float ey = fmaf(yf, r[3] - r[2], r[2]);
    float ez = fmaf(zf, r[5] - r[4], r[4]);
    float t0 = fmaf(xf, r[7] - r[6], r[6]);
    float t1 = fmaf(xf, r[9] - r[8], r[8]);
    float exy = fmaf(yf, t1 - t0, t0);
    float u0 = fmaf(yf, r[11] - r[10], r[10]);
    float u1 = fmaf(yf, r[13] - r[12], r[12]);
    float eyz = fmaf(zf, u1 - u0, u0);
    float v0 = fmaf(xf, r[15] - r[14], r[14]);
    float v1 = fmaf(xf, r[17] - r[16], r[16]);
    float exz = fmaf(zf, v1 - v0, v0);
    return ex * eyz + ey * exz + ez * exy;
}

// ---------------------------------------------------------------------------
// Main kernel.
// Phase 1 (lane=channel): gather+interp (4-deep ring), bf16 hi/lo split into
//   per-warp A tiles [32 pts x 32 ch].
// Phase 2: mma.sync m16n8k16 bf16 3-pass (ah.bh + al.bh + ah.bl), fp32 accum
//   init with b1; epilogue relu + W2 in fragment layout, quad shfl-reduce.
// Weights: W1^T as bf16 hi/lo [n][k] tiles (80B padded rows, conflict-free
//   ldmatrix); staged once per block.
// ---------------------------------------------------------------------------
#define WSTRIDE 40   // bf16 elems per W row (80B, 16B-aligned, bank-rotating)

__global__ __launch_bounds__(128, 5)
void k_tensorf(const float* __restrict__ coords,
               const float* __restrict__ W1,
               const float* __restrict__ b1,
               const float* __restrict__ W2,
               const float* __restrict__ b2,
               float* __restrict__ out, int P)
{
    __shared__ __align__(16) __nv_bfloat16 sWh[128 * WSTRIDE];  // 10240 B
    __shared__ __align__(16) __nv_bfloat16 sWl[128 * WSTRIDE];  // 10240 B
    __shared__ __align__(16) __nv_bfloat16 sAh[4][32 * 32];     // 8192 B
    __shared__ __align__(16) __nv_bfloat16 sAl[4][32 * 32];     // 8192 B
    __shared__ __align__(16) float2 sb1[64];                    // 512 B
    __shared__ __align__(16) float2 sw2[64];                    // 512 B
    __shared__ __align__(16) float4 sPf[4][32];                 // 2048 B

    const int tid  = threadIdx.x;
    const int lane = tid & 31;
    const int wib  = tid >> 5;
    const unsigned FULL = 0xffffffffu;

    // --- Stage W1^T (bf16 hi/lo), b1/W2 pairs ---
    for (int idx = tid; idx < 32 * 128; idx += 128) {
        int k = idx >> 7, n = idx & 127;      // W1 is [k][n] row-major
        float w = W1[idx];
        __nv_bfloat16 hh = __float2bfloat16(w);
        __nv_bfloat16 ll = __float2bfloat16(w - __bfloat162float(hh));
        sWh[n * WSTRIDE + k] = hh;
        sWl[n * WSTRIDE + k] = ll;
    }
    if (tid < 64) {
        sb1[tid] = make_float2(b1[2 * tid], b1[2 * tid + 1]);
        sw2[tid] = make_float2(W2[2 * tid], W2[2 * tid + 1]);
    }
    __syncthreads();

    const float b2v = __ldg(b2);
    __nv_bfloat16* myAh = sAh[wib];
    __nv_bfloat16* myAl = sAl[wib];
    float4* myP = sPf[wib];

    const uint32_t whB = smem_to_u32(sWh);
    const uint32_t wlB = smem_to_u32(sWl);
    const uint32_t ahB = smem_to_u32(myAh);
    const uint32_t alB = smem_to_u32(myAl);

    // Fragment address offsets (canonical ldmatrix patterns)
    const int g4  = lane >> 2;                             // accum row group
    const int tig = lane & 3;
    const uint32_t aoff = ((lane & 15) * 32 + (lane >> 4) * 8) * 2; // row*64B + colblk*16B
    const uint32_t boff = ((lane >> 4) * 8 + (lane & 7)) * (WSTRIDE * 2)
                        + ((lane >> 3) & 1) * 16;          // n-row*80B + khalf*16B

    const int gwarp = blockIdx.x * 4 + wib;
    const int nwarp = gridDim.x * 4;
    const int ngroups = (P + 31) >> 5;

    for (int g = gwarp; g < ngroups; g += nwarp) {
        const int base = g << 5;
        const int myp  = base + lane;
        const int pc   = (myp < P) ? myp : P - 1;

        float x = __ldg(coords + 3 * pc + 0);
        float y = __ldg(coords + 3 * pc + 1);
        float z = __ldg(coords + 3 * pc + 2);
        int xi, yi, zi; float xf, yf, zf;
        grid_coord(x, xi, xf);
        grid_coord(y, yi, yf);
        grid_coord(z, zi, zf);
        int packed = xi | (yi << 9) | (zi << 18);
        myP[lane] = make_float4(xf, yf, zf, __int_as_float(packed));
        __syncwarp();

        // ---- Phase 1: gather + interp, 4-deep ring ----
        float rb[4][18];
        #pragma unroll
        for (int k = 0; k < 4; k++) {
            float4 p = myP[k];
            int ip = __float_as_int(p.w);
            gather18(lane, ip & 511, (ip >> 9) & 511, ip >> 18, rb[k]);
        }
        #pragma unroll 1
        for (int i = 0; i < 32; i += 4) {
            #pragma unroll
            for (int k = 0; k < 4; k++) {
                int pi = i + k;
                float4 pf = myP[pi];
                float f = interp_feat(rb[k], pf.x, pf.y, pf.z);
                __nv_bfloat16 hh = __float2bfloat16(f);
                __nv_bfloat16 ll = __float2bfloat16(f - __bfloat162float(hh));
                myAh[pi * 32 + lane] = hh;
                myAl[pi * 32 + lane] = ll;
                int np = pi + 4;
                if (np < 32) {
                    float4 pn = myP[np];
                    int ip = __float_as_int(pn.w);
                    gather18(lane, ip & 511, (ip >> 9) & 511, ip >> 18, rb[k]);
                }
            }
        }
        __syncwarp();

        // ---- Phase 2: mma ----
        // A-hi fragments (m-tile x k-tile), kept live across chunks
        uint32_t ah[2][2][4];
        #pragma unroll
        for (int mt = 0; mt < 2; mt++)
            #pragma unroll
            for (int kt = 0; kt < 2; kt++)
                ldsm_x4(ah[mt][kt][0], ah[mt][kt][1], ah[mt][kt][2], ah[mt][kt][3],
                        ahB + aoff + mt * 1024 + kt * 32);

        float sr0 = 0.f, sr1 = 0.f, sr2 = 0.f, sr3 = 0.f;

        #pragma unroll 1
        for (int nc = 0; nc < 4; nc++) {
            // accum init with b1
            float acc[2][4][4];
            #pragma unroll
            for (int nt = 0; nt < 4; nt++) {
                float2 bp = sb1[nc * 16 + nt * 4 + tig];
                #pragma unroll
                for (int mt = 0; mt < 2; mt++) {
                    acc[mt][nt][0] = bp.x; acc[mt][nt][1] = bp.y;
                    acc[mt][nt][2] = bp.x; acc[mt][nt][3] = bp.y;
                }
            }

            #pragma unroll
            for (int kt = 0; kt < 2; kt++) {
                uint32_t bh[4][2], bl[4][2], al2[2][4];
                uint32_t wbase = boff + (uint32_t)(nc * 32) * (WSTRIDE * 2) + kt * 32;
                ldsm_x4(bh[0][0], bh[0][1], bh[1][0], bh[1][1], whB + wbase);
                ldsm_x4(bh[2][0], bh[2][1], bh[3][0], bh[3][1],
                        whB + wbase + 16u * (WSTRIDE * 2));
                ldsm_x4(bl[0][0], bl[0][1], bl[1][0], bl[1][1], wlB + wbase);
                ldsm_x4(bl[2][0], bl[2][1], bl[3][0], bl[3][1],
                        wlB + wbase + 16u * (WSTRIDE * 2));
                #pragma unroll
                for (int mt = 0; mt < 2; mt++)
                    ldsm_x4(al2[mt][0], al2[mt][1], al2[mt][2], al2[mt][3],
                            alB + aoff + mt * 1024 + kt * 32);

                #pragma unroll
                for (int mt = 0; mt < 2; mt++)
                    #pragma unroll
                    for (int nt = 0; nt < 4; nt++) {
                        mma_bf16(acc[mt][nt][0], acc[mt][nt][1], acc[mt][nt][2], acc[mt][nt][3],
                                 ah[mt][kt][0], ah[mt][kt][1], ah[mt][kt][2], ah[mt][kt][3],
                                 bh[nt][0], bh[nt][1]);
                        mma_bf16(acc[mt][nt][0], acc[mt][nt][1], acc[mt][nt][2], acc[mt][nt][3],
                                 al2[mt][0], al2[mt][1], al2[mt][2], al2[mt][3],
                                 bh[nt][0], bh[nt][1]);
                        mma_bf16(acc[mt][nt][0], acc[mt][nt][1], acc[mt][nt][2], acc[mt][nt][3],
                                 ah[mt][kt][0], ah[mt][kt][1], ah[mt][kt][2], ah[mt][kt][3],
                                 bl[nt][0], bl[nt][1]);
                    }
            }

            // epilogue: relu + W2 dot, per fragment
            #pragma unroll
            for (int nt = 0; nt < 4; nt++) {
                float2 wp = sw2[nc * 16 + nt * 4 + tig];
                sr0 = fmaf(fmaxf(acc[0][nt][0], 0.f), wp.x, sr0);
                sr0 = fmaf(fmaxf(acc[0][nt][1], 0.f), wp.y, sr0);
                sr1 = fmaf(fmaxf(acc[0][nt][2], 0.f), wp.x, sr1);
                sr1 = fmaf(fmaxf(acc[0][nt][3], 0.f), wp.y, sr1);
                sr2 = fmaf(fmaxf(acc[1][nt][0], 0.f), wp.x, sr2);
                sr2 = fmaf(fmaxf(acc[1][nt][1], 0.f), wp.y, sr2);
                sr3 = fmaf(fmaxf(acc[1][nt][2], 0.f), wp.x, sr3);
                sr3 = fmaf(fmaxf(acc[1][nt][3], 0.f), wp.y, sr3);
            }
        }

        // quad reduction: lanes g4*4+{0..3} hold disjoint n-columns of the
        // same rows {g4, g4+8, g4+16, g4+24}
        #pragma unroll
        for (int d = 1; d <= 2; d <<= 1) {
            sr0 += __shfl_xor_sync(FULL, sr0, d);
            sr1 += __shfl_xor_sync(FULL, sr1, d);
            sr2 += __shfl_xor_sync(FULL, sr2, d);
            sr3 += __shfl_xor_sync(FULL, sr3, d);
        }
        float sv = (tig == 0) ? sr0 : (tig == 1) ? sr1 : (tig == 2) ? sr2 : sr3;
        int row = tig * 8 + g4;
        int op = base + row;
        if (op < P) out[op] = sv + b2v;

        __syncwarp();   // protect myP / A tiles before next group's writes
    }
}

// ---------------------------------------------------------------------------
extern "C" void kernel_launch(void* const* d_in, const int* in_sizes, int n_in,
                              void* d_out, int out_size)
{
    const float* coords   = (const float*)d_in[0];
    const float* line_x   = (const float*)d_in[1];
    const float* line_y   = (const float*)d_in[2];
    const float* line_z   = (const float*)d_in[3];
    const float* plane_xy = (const float*)d_in[4];
    const float* plane_yz = (const float*)d_in[5];
    const float* plane_xz = (const float*)d_in[6];
    const float* W1       = (const float*)d_in[7];
    const float* b1       = (const float*)d_in[8];
    const float* W2       = (const float*)d_in[9];
    const float* b2       = (const float*)d_in[10];
    float* out = (float*)d_out;

    int P = in_sizes[0] / 3;

    k_transpose_planes<<<dim3(NL / 128, NL, 3), dim3(32, 16)>>>(plane_xy, plane_yz, plane_xz);
    k_transpose_lines<<<dim3(NL / 32, 1, 3), dim3(32, 32)>>>(line_x, line_y, line_z);

    // Persistent grid-stride over 32-point groups (5 CTAs/SM on 152 SMs).
    int blocks = 760;
    k_tensorf<<<blocks, 128>>>(coords, W1, b1, W2, b2, out, P);
}

// round 17
// speedup vs baseline: 3.5461x; 1.2246x over previous
#include <cuda_runtime.h>
#include <cuda_fp16.h>
#include <cuda_bf16.h>
#include <math.h>
#include <cstdint>

#define NL 512
#define CL 32

// Scratch: planes transposed to [H][W][C] fp16 (64B per texel), lines [N][C] fp16.
__device__ __half g_planes[3][(size_t)NL * NL * CL];   // 48 MB
__device__ __half g_lines[3][NL * CL];

// ---------------------------------------------------------------------------
// Transpose planes [C,H,W] fp32 -> [H,W,C] fp16. Block (32,16): 32c x 128w.
// ---------------------------------------------------------------------------
__global__ void k_transpose_planes(const float* __restrict__ pxy,
                                   const float* __restrict__ pyz,
                                   const float* __restrict__ pxz)
{
    __shared__ float tile[CL][129];
    int plane = blockIdx.z;
    const float* src = (plane == 0) ? pxy : (plane == 1) ? pyz : pxz;
    int h  = blockIdx.y;
    int w0 = blockIdx.x * 128;

    #pragma unroll
    for (int cy = threadIdx.y; cy < CL; cy += 16) {
        float4 v = *(const float4*)(src + (size_t)cy * (NL * NL) + (size_t)h * NL
                                    + w0 + threadIdx.x * 4);
        tile[cy][threadIdx.x * 4 + 0] = v.x;
        tile[cy][threadIdx.x * 4 + 1] = v.y;
        tile[cy][threadIdx.x * 4 + 2] = v.z;
        tile[cy][threadIdx.x * 4 + 3] = v.w;
    }
    __syncthreads();

    int c = threadIdx.x;
    #pragma unroll
    for (int w = threadIdx.y; w < 128; w += 16) {
        g_planes[plane][((size_t)h * NL + (w0 + w)) * CL + c] =
            __float2half_rn(tile[c][w]);
    }
}

__global__ void k_transpose_lines(const float* __restrict__ lx,
                                  const float* __restrict__ ly,
                                  const float* __restrict__ lz)
{
    __shared__ float tile[32][33];
    int plane = blockIdx.z;
    const float* src = (plane == 0) ? lx : (plane == 1) ? ly : lz;
    int n0 = blockIdx.x * 32;
    tile[threadIdx.y][threadIdx.x] = src[threadIdx.x * NL + n0 + threadIdx.y];
    __syncthreads();
    g_lines[plane][(n0 + threadIdx.y) * CL + threadIdx.x] =
        __float2half_rn(tile[threadIdx.y][threadIdx.x]);
}

// ---------------------------------------------------------------------------
// mma.sync / ldmatrix helpers (sm_80+ features; legal on plain sm_103 target)
// ---------------------------------------------------------------------------
__device__ __forceinline__ uint32_t smem_to_u32(const void* p) {
    uint32_t a;
    asm("{ .reg .u64 t; cvta.to.shared.u64 t, %1; cvt.u32.u64 %0, t; }"
        : "=r"(a) : "l"(p));
    return a;
}

__device__ __forceinline__ void ldsm_x4(uint32_t& r0, uint32_t& r1,
                                        uint32_t& r2, uint32_t& r3, uint32_t addr)
{
    asm volatile("ldmatrix.sync.aligned.m8n8.x4.shared.b16 {%0,%1,%2,%3}, [%4];"
                 : "=r"(r0), "=r"(r1), "=r"(r2), "=r"(r3) : "r"(addr));
}

__device__ __forceinline__ void mma_bf16(float& c0, float& c1, float& c2, float& c3,
                                         uint32_t a0, uint32_t a1, uint32_t a2, uint32_t a3,
                                         uint32_t b0, uint32_t b1)
{
    asm volatile("mma.sync.aligned.m16n8k16.row.col.f32.bf16.bf16.f32 "
                 "{%0,%1,%2,%3}, {%4,%5,%6,%7}, {%8,%9}, {%0,%1,%2,%3};"
                 : "+f"(c0), "+f"(c1), "+f"(c2), "+f"(c3)
                 : "r"(a0), "r"(a1), "r"(a2), "r"(a3), "r"(b0), "r"(b1));
}

// ---------------------------------------------------------------------------
__device__ __forceinline__ void grid_coord(float g, int& i0, float& f)
{
    float ix = (g + 1.0f) * 0.5f * (float)(NL - 1);
    float fl = floorf(ix);
    int   i  = (int)fl;
    float fr = ix - fl;
    if (i < 0)      { i = 0;      fr = 0.0f; }
    if (i > NL - 2) { i = NL - 2; fr = 1.0f; }
    i0 = i; f = fr;
}

// 18 coalesced fp16 channel-loads for one point (lane = channel)
__device__ __forceinline__ void gather18(int lane, int xi, int yi, int zi, float* r)
{
    const __half* L0 = g_lines[0] + xi * CL + lane;
    const __half* L1 = g_lines[1] + yi * CL + lane;
    const __half* L2 = g_lines[2] + zi * CL + lane;
    r[0] = __half2float(L0[0]);  r[1] = __half2float(L0[CL]);
    r[2] = __half2float(L1[0]);  r[3] = __half2float(L1[CL]);
    r[4] = __half2float(L2[0]);  r[5] = __half2float(L2[CL]);

    const __half* pxy = g_planes[0] + ((yi * NL + xi) * CL + lane); // h=y,w=x
    const __half* pyz = g_planes[1] + ((zi * NL + yi) * CL + lane); // h=z,w=y
    const __half* pxz = g_planes[2] + ((zi * NL + xi) * CL + lane); // h=z,w=x
    r[6]  = __half2float(pxy[0]);      r[7]  = __half2float(pxy[CL]);
    r[8]  = __half2float(pxy[NL*CL]);  r[9]  = __half2float(pxy[NL*CL + CL]);
    r[10] = __half2float(pyz[0]);      r[11] = __half2float(pyz[CL]);
    r[12] = __half2float(pyz[NL*CL]);  r[13] = __half2float(pyz[NL*CL + CL]);
    r[14] = __half2float(pxz[0]);      r[15] = __half2float(pxz[CL]);
    r[16] = __half2float(pxz[NL*CL]);  r[17] = __half2float(pxz[NL*CL + CL]);
}

__device__ __forceinline__ float interp_feat(const float* r, float xf, float yf, float zf)
{
    float ex = fmaf(xf, r[1] - r[0], r[0]);
    float ey = fmaf(yf, r[3] - r[2], r[2]);
    float ez = fmaf(zf, r[5] - r[4], r[4]);
    float t0 = fmaf(xf, r[7] - r[6], r[6]);
    float t1 = fmaf(xf, r[9] - r[8], r[8]);
    float exy = fmaf(yf, t1 - t0, t0);
    float u0 = fmaf(yf, r[11] - r[10], r[10]);
    float u1 = fmaf(yf, r[13] - r[12], r[12]);
    float eyz = fmaf(zf, u1 - u0, u0);
    float v0 = fmaf(xf, r[15] - r[14], r[14]);
    float v1 = fmaf(xf, r[17] - r[16], r[16]);
    float exz = fmaf(zf, v1 - v0, v0);
    return ex * eyz + ey * exz + ez * exy;
}

// ---------------------------------------------------------------------------
// Main kernel (structure from R16, measured 262us main):
// Phase 1 (lane=channel): fp16 gather + fp32 interp (4-deep ring), bf16 hi/lo
//   split into per-warp A tiles [32 pts x 32 ch], rows padded to 80B
//   (stride 40) for conflict-free ldmatrix (banks 20r mod 32 distinct).
// Phase 2: mma.sync m16n8k16 bf16 3-pass (ah.bh + al.bh + ah.bl), fp32 accum
//   init with b1; epilogue relu + W2 in fragment layout, quad shfl-reduce.
// ---------------------------------------------------------------------------
#define WSTRIDE 40   // bf16 elems per row (80B, 16B-aligned, bank-rotating)

__global__ __launch_bounds__(128, 5)
void k_tensorf(const float* __restrict__ coords,
               const float* __restrict__ W1,
               const float* __restrict__ b1,
               const float* __restrict__ W2,
               const float* __restrict__ b2,
               float* __restrict__ out, int P)
{
    __shared__ __align__(16) __nv_bfloat16 sWh[128 * WSTRIDE];  // 10240 B
    __shared__ __align__(16) __nv_bfloat16 sWl[128 * WSTRIDE];  // 10240 B
    __shared__ __align__(16) __nv_bfloat16 sAh[4][32 * WSTRIDE]; // 10240 B
    __shared__ __align__(16) __nv_bfloat16 sAl[4][32 * WSTRIDE]; // 10240 B
    __shared__ __align__(16) float2 sb1[64];                    // 512 B
    __shared__ __align__(16) float2 sw2[64];                    // 512 B
    __shared__ __align__(16) float4 sPf[4][32];                 // 2048 B

    const int tid  = threadIdx.x;
    const int lane = tid & 31;
    const int wib  = tid >> 5;
    const unsigned FULL = 0xffffffffu;

    // --- Stage W1^T (bf16 hi/lo), b1/W2 pairs ---
    for (int idx = tid; idx < 32 * 128; idx += 128) {
        int k = idx >> 7, n = idx & 127;      // W1 is [k][n] row-major
        float w = W1[idx];
        __nv_bfloat16 hh = __float2bfloat16(w);
        __nv_bfloat16 ll = __float2bfloat16(w - __bfloat162float(hh));
        sWh[n * WSTRIDE + k] = hh;
        sWl[n * WSTRIDE + k] = ll;
    }
    if (tid < 64) {
        sb1[tid] = make_float2(b1[2 * tid], b1[2 * tid + 1]);
        sw2[tid] = make_float2(W2[2 * tid], W2[2 * tid + 1]);
    }
    __syncthreads();

    const float b2v = __ldg(b2);
    __nv_bfloat16* myAh = sAh[wib];
    __nv_bfloat16* myAl = sAl[wib];
    float4* myP = sPf[wib];

    const uint32_t whB = smem_to_u32(sWh);
    const uint32_t wlB = smem_to_u32(sWl);
    const uint32_t ahB = smem_to_u32(myAh);
    const uint32_t alB = smem_to_u32(myAl);

    // Fragment address offsets
    const int g4  = lane >> 2;
    const int tig = lane & 3;
    const uint32_t aoff = (uint32_t)(lane & 15) * (WSTRIDE * 2)
                        + (uint32_t)(lane >> 4) * 16;           // row*80B + kblk*16B
    const uint32_t boff = ((lane >> 4) * 8 + (lane & 7)) * (WSTRIDE * 2)
                        + ((lane >> 3) & 1) * 16;               // n-row*80B + khalf*16B
    const uint32_t AMT = 16u * (WSTRIDE * 2);                   // 16 rows

    const int gwarp = blockIdx.x * 4 + wib;
    const int nwarp = gridDim.x * 4;
    const int ngroups = (P + 31) >> 5;

    for (int g = gwarp; g < ngroups; g += nwarp) {
        const int base = g << 5;
        const int myp  = base + lane;
        const int pc   = (myp < P) ? myp : P - 1;

        float x = __ldg(coords + 3 * pc + 0);
        float y = __ldg(coords + 3 * pc + 1);
        float z = __ldg(coords + 3 * pc + 2);
        int xi, yi, zi; float xf, yf, zf;
        grid_coord(x, xi, xf);
        grid_coord(y, yi, yf);
        grid_coord(z, zi, zf);
        int packed = xi | (yi << 9) | (zi << 18);
        myP[lane] = make_float4(xf, yf, zf, __int_as_float(packed));
        __syncwarp();

        // ---- Phase 1: gather + interp, 4-deep ring ----
        float rb[4][18];
        #pragma unroll
        for (int k = 0; k < 4; k++) {
            float4 p = myP[k];
            int ip = __float_as_int(p.w);
            gather18(lane, ip & 511, (ip >> 9) & 511, ip >> 18, rb[k]);
        }
        #pragma unroll 1
        for (int i = 0; i < 32; i += 4) {
            #pragma unroll
            for (int k = 0; k < 4; k++) {
                int pi = i + k;
                float4 pf = myP[pi];
                float f = interp_feat(rb[k], pf.x, pf.y, pf.z);
                __nv_bfloat16 hh = __float2bfloat16(f);
                __nv_bfloat16 ll = __float2bfloat16(f - __bfloat162float(hh));
                myAh[pi * WSTRIDE + lane] = hh;
                myAl[pi * WSTRIDE + lane] = ll;
                int np = pi + 4;
                if (np < 32) {
                    float4 pn = myP[np];
                    int ip = __float_as_int(pn.w);
                    gather18(lane, ip & 511, (ip >> 9) & 511, ip >> 18, rb[k]);
                }
            }
        }
        __syncwarp();

        // ---- Phase 2: mma ----
        uint32_t ah[2][2][4];
        #pragma unroll
        for (int mt = 0; mt < 2; mt++)
            #pragma unroll
            for (int kt = 0; kt < 2; kt++)
                ldsm_x4(ah[mt][kt][0], ah[mt][kt][1], ah[mt][kt][2], ah[mt][kt][3],
                        ahB + aoff + mt * AMT + kt * 32);

        float sr0 = 0.f, sr1 = 0.f, sr2 = 0.f, sr3 = 0.f;

        #pragma unroll 1
        for (int nc = 0; nc < 4; nc++) {
            float acc[2][4][4];
            #pragma unroll
            for (int nt = 0; nt < 4; nt++) {
                float2 bp = sb1[nc * 16 + nt * 4 + tig];
                #pragma unroll
                for (int mt = 0; mt < 2; mt++) {
                    acc[mt][nt][0] = bp.x; acc[mt][nt][1] = bp.y;
                    acc[mt][nt][2] = bp.x; acc[mt][nt][3] = bp.y;
                }
            }

            #pragma unroll
            for (int kt = 0; kt < 2; kt++) {
                uint32_t bh[4][2], bl[4][2], al2[2][4];
                uint32_t wbase = boff + (uint32_t)(nc * 32) * (WSTRIDE * 2) + kt * 32;
                ldsm_x4(bh[0][0], bh[0][1], bh[1][0], bh[1][1], whB + wbase);
                ldsm_x4(bh[2][0], bh[2][1], bh[3][0], bh[3][1], whB + wbase + AMT);
                ldsm_x4(bl[0][0], bl[0][1], bl[1][0], bl[1][1], wlB + wbase);
                ldsm_x4(bl[2][0], bl[2][1], bl[3][0], bl[3][1], wlB + wbase + AMT);
                #pragma unroll
                for (int mt = 0; mt < 2; mt++)
                    ldsm_x4(al2[mt][0], al2[mt][1], al2[mt][2], al2[mt][3],
                            alB + aoff + mt * AMT + kt * 32);

                #pragma unroll
                for (int mt = 0; mt < 2; mt++)
                    #pragma unroll
                    for (int nt = 0; nt < 4; nt++) {
                        mma_bf16(acc[mt][nt][0], acc[mt][nt][1], acc[mt][nt][2], acc[mt][nt][3],
                                 ah[mt][kt][0], ah[mt][kt][1], ah[mt][kt][2], ah[mt][kt][3],
                                 bh[nt][0], bh[nt][1]);
                        mma_bf16(acc[mt][nt][0], acc[mt][nt][1], acc[mt][nt][2], acc[mt][nt][3],
                                 al2[mt][0], al2[mt][1], al2[mt][2], al2[mt][3],
                                 bh[nt][0], bh[nt][1]);
                        mma_bf16(acc[mt][nt][0], acc[mt][nt][1], acc[mt][nt][2], acc[mt][nt][3],
                                 ah[mt][kt][0], ah[mt][kt][1], ah[mt][kt][2], ah[mt][kt][3],
                                 bl[nt][0], bl[nt][1]);
                    }
            }

            #pragma unroll
            for (int nt = 0; nt < 4; nt++) {
                float2 wp = sw2[nc * 16 + nt * 4 + tig];
                sr0 = fmaf(fmaxf(acc[0][nt][0], 0.f), wp.x, sr0);
                sr0 = fmaf(fmaxf(acc[0][nt][1], 0.f), wp.y, sr0);
                sr1 = fmaf(fmaxf(acc[0][nt][2], 0.f), wp.x, sr1);
                sr1 = fmaf(fmaxf(acc[0][nt][3], 0.f), wp.y, sr1);
                sr2 = fmaf(fmaxf(acc[1][nt][0], 0.f), wp.x, sr2);
                sr2 = fmaf(fmaxf(acc[1][nt][1], 0.f), wp.y, sr2);
                sr3 = fmaf(fmaxf(acc[1][nt][2], 0.f), wp.x, sr3);
                sr3 = fmaf(fmaxf(acc[1][nt][3], 0.f), wp.y, sr3);
            }
        }

        #pragma unroll
        for (int d = 1; d <= 2; d <<= 1) {
            sr0 += __shfl_xor_sync(FULL, sr0, d);
            sr1 += __shfl_xor_sync(FULL, sr1, d);
            sr2 += __shfl_xor_sync(FULL, sr2, d);
            sr3 += __shfl_xor_sync(FULL, sr3, d);
        }
        float sv = (tig == 0) ? sr0 : (tig == 1) ? sr1 : (tig == 2) ? sr2 : sr3;
        int row = tig * 8 + g4;
        int op = base + row;
        if (op < P) out[op] = sv + b2v;

        __syncwarp();   // protect myP / A tiles before next group's writes
    }
}

// ---------------------------------------------------------------------------
extern "C" void kernel_launch(void* const* d_in, const int* in_sizes, int n_in,
                              void* d_out, int out_size)
{
    const float* coords   = (const float*)d_in[0];
    const float* line_x   = (const float*)d_in[1];
    const float* line_y   = (const float*)d_in[2];
    const float* line_z   = (const float*)d_in[3];
    const float* plane_xy = (const float*)d_in[4];
    const float* plane_yz = (const float*)d_in[5];
    const float* plane_xz = (const float*)d_in[6];
    const float* W1       = (const float*)d_in[7];
    const float* b1       = (const float*)d_in[8];
    const float* W2       = (const float*)d_in[9];
    const float* b2       = (const float*)d_in[10];
    float* out = (float*)d_out;

    int P = in_sizes[0] / 3;

    k_transpose_planes<<<dim3(NL / 128, NL, 3), dim3(32, 16)>>>(plane_xy, plane_yz, plane_xz);
    k_transpose_lines<<<dim3(NL / 32, 1, 3), dim3(32, 32)>>>(line_x, line_y, line_z);

    // Persistent grid-stride over 32-point groups (5 CTAs/SM on 152 SMs).
    int blocks = 760;
    k_tensorf<<<blocks, 128>>>(coords, W1, b1, W2, b2, out, P);
}